// round 4
// baseline (speedup 1.0000x reference)
#include <cuda_runtime.h>
#include <math.h>

#define NN 3200
#define EE 50000
#define NS 32
#define NV 16
#define DD 80
#define HID 128
#define WNUM 2304
#define EPS 1e-8f
#define A1C 0.125f               // 1/sqrt(64)
#define A2C 0.17677669529663687f // 1/sqrt(32)
#define A3C 0.125f
#define A4C 0.17677669529663687f
#define ISQ3 0.5773502691896258f
#define PI_F 3.14159265358979323846f
#define RS32 0.17677669529663687f
#define RS16 0.25f

typedef unsigned long long u64;

// ---------------- scratch ----------------
__device__ float g_xnorm[NN * DD];
__device__ float g_h[EE * HID];
__device__ float g_edgew[EE];
__device__ float g_agg[NN * DD];
__device__ float g_den[NN];

__device__ __forceinline__ float siluf(float x) { return x / (1.f + __expf(-x)); }
__device__ __forceinline__ float sigmf(float x) { return 1.f / (1.f + __expf(-x)); }

__device__ __forceinline__ u64 dup2(float x) {
    u64 r; asm("mov.b64 %0, {%1, %1};" : "=l"(r) : "f"(x)); return r;
}
__device__ __forceinline__ void ffma2(u64& d, u64 a, u64 b) {
    asm("fma.rn.f32x2 %0, %1, %2, %0;" : "+l"(d) : "l"(a), "l"(b));
}
__device__ __forceinline__ float2 unpk(u64 v) {
    float2 r; asm("mov.b64 {%0, %1}, %2;" : "=f"(r.x), "=f"(r.y) : "l"(v)); return r;
}
__device__ __forceinline__ void cpa16(unsigned sa, const void* g) {
    asm volatile("cp.async.cg.shared.global [%0], [%1], 16;" :: "r"(sa), "l"(g));
}

// ---------------- kZ ----------------
__global__ void kZ() {
    int i = blockIdx.x * 256 + threadIdx.x;
    if (i < NN * DD) g_agg[i] = 0.f;
    if (i < NN) g_den[i] = 0.f;
}

// ---------------- kA: irrep norm ----------------
__global__ void __launch_bounds__(256) kA(const float* __restrict__ x,
                                          const float* __restrict__ nw,
                                          const float* __restrict__ nb) {
    int warp = (blockIdx.x * blockDim.x + threadIdx.x) >> 5;
    int lane = threadIdx.x & 31;
    if (warp >= NN) return;
    const float* xr = x + warp * DD;
    float s = xr[lane];
    float m = s;
    #pragma unroll
    for (int o = 16; o; o >>= 1) m += __shfl_xor_sync(0xffffffffu, m, o);
    m *= (1.f / 32.f);
    float d = s - m;
    float v = d * d;
    #pragma unroll
    for (int o = 16; o; o >>= 1) v += __shfl_xor_sync(0xffffffffu, v, o);
    v *= (1.f / 32.f);
    float sn = d * rsqrtf(v + EPS);
    g_xnorm[warp * DD + lane] = sn * nw[lane] + nb[lane];
    if (lane < NV) {
        int b = NS + lane * 3;
        float a0 = xr[b], a1 = xr[b + 1], a2 = xr[b + 2];
        float r = rsqrtf((a0 * a0 + a1 * a1 + a2 * a2) * (1.f / 3.f) + EPS);
        int gb = warp * DD + b;
        g_xnorm[gb]     = a0 * r * nw[b]     + nb[b];
        g_xnorm[gb + 1] = a1 * r * nw[b + 1] + nb[b + 1];
        g_xnorm[gb + 2] = a2 * r * nw[b + 2] + nb[b + 2];
    }
}

// ---------------- kB: edge MLP + gate + cutoff + den (unchanged, verified) ----
#define KB_GROUPS 592
__global__ void __launch_bounds__(256) kB(const float* __restrict__ rbf,
                                          const float* __restrict__ elen,
                                          const int* __restrict__ edst,
                                          const float* __restrict__ mw1, const float* __restrict__ mb1,
                                          const float* __restrict__ mw2, const float* __restrict__ mb2,
                                          const float* __restrict__ gw1, const float* __restrict__ gb1,
                                          const float* __restrict__ gw2, const float* __restrict__ gb2) {
    extern __shared__ float sm[];
    float* s_mw1 = sm;
    float* s_mw2 = s_mw1 + 16 * HID;
    float* s_gw1 = s_mw2 + HID * HID;
    float* s_gw2 = s_gw1 + 16 * HID;
    float* s_mb1 = s_gw2 + HID;
    float* s_mb2 = s_mb1 + HID;
    float* s_gb1 = s_mb2 + HID;
    float* s_grp = s_gb1 + HID;

    int tid = threadIdx.x;
    for (int i = tid; i < 16 * HID; i += 256) { s_mw1[i] = mw1[i]; s_gw1[i] = gw1[i]; }
    for (int i = tid; i < HID * HID; i += 256) s_mw2[i] = mw2[i];
    for (int i = tid; i < HID; i += 256) {
        s_gw2[i] = gw2[i]; s_mb1[i] = mb1[i]; s_mb2[i] = mb2[i]; s_gb1[i] = gb1[i];
    }
    int sub = tid >> 7;
    int c = tid & 127;
    float* s_rbf = s_grp + sub * 152;
    float* s_h1  = s_rbf + 16;
    float* s_red = s_h1 + 128;
    __syncthreads();

    int gid = blockIdx.x * 2 + sub;
    int iters = (EE + KB_GROUPS - 1) / KB_GROUPS;
    float gb2v = gb2[0];
    for (int it = 0; it < iters; ++it) {
        int e = it * KB_GROUPS + gid;
        bool ok = (e < EE);
        if (ok && c < 16) s_rbf[c] = rbf[e * 16 + c];
        __syncthreads();
        if (ok) {
            float a1 = s_mb1[c], ag = s_gb1[c];
            #pragma unroll
            for (int r = 0; r < 16; ++r) {
                float rv = s_rbf[r];
                a1 += rv * s_mw1[r * HID + c];
                ag += rv * s_gw1[r * HID + c];
            }
            a1 = siluf(a1);
            ag = siluf(ag);
            s_h1[c] = a1;
            float p = ag * s_gw2[c];
            #pragma unroll
            for (int o = 16; o; o >>= 1) p += __shfl_xor_sync(0xffffffffu, p, o);
            if ((c & 31) == 0) s_red[c >> 5] = p;
        }
        __syncthreads();
        if (ok) {
            float a = s_mb2[c];
            #pragma unroll 8
            for (int k = 0; k < HID; ++k) a += s_h1[k] * s_mw2[k * HID + c];
            g_h[e * HID + c] = siluf(a);
            if (c == 0) {
                float gsum = s_red[0] + s_red[1] + s_red[2] + s_red[3];
                float gate = sigmf(gsum + gb2v);
                float len = elen[e];
                float cut = (len <= 5.0f) ? 0.5f * (__cosf(PI_F * len * 0.2f) + 1.0f) : 0.0f;
                float ew = cut * gate;
                g_edgew[e] = ew;
                atomicAdd(&g_den[edst[e]], ew);
            }
        }
        __syncthreads();
    }
}

// ---------------- kC: FFMA2 fused GEMM + contraction + scatter ----------------
// 512 threads, 64-edge tile, 36 chunks of 64 cols, cp.async double-buffered B.
// A tile stored DUPLICATED in smem (8B per value) so inner loop needs no MOVs.
#define TEDGE 64
#define HPITCH 66   // u64 elems per k-row (64 + 2 pad); even, 16B-aligned rows
#define TPITCH 68   // floats per tpw row (64 + 4 pad); %4==0 for float4 stores
__global__ void __launch_bounds__(512, 1) kC(const int* __restrict__ esrc,
                                             const int* __restrict__ edst,
                                             const float* __restrict__ esh,
                                             const float* __restrict__ mw3,
                                             const float* __restrict__ mb3) {
    extern __shared__ char smraw[];
    u64*   s_hd  = (u64*)smraw;                    // [128][HPITCH] dup-A  67584B
    float* s_B   = (float*)(s_hd + 128 * HPITCH);  // 2 x [128][64]        65536B
    float* s_tp  = s_B + 2 * 128 * 64;             // [64][TPITCH]
    float* s_A   = s_tp + 64 * TPITCH;             // [64][81]
    float* s_xs  = s_A + 64 * 81;                  // [64][32]
    float* s_in2 = s_xs + 64 * 32;                 // [64][16]
    float* s_xv  = s_in2 + 64 * 16;                // [64][48]
    float* s_sh0 = s_xv + 64 * 48;                 // 64
    float* s_sh1 = s_sh0 + 64;                     // [64][3]
    float* s_ew  = s_sh1 + 64 * 3;                 // 64
    int*   s_dst = (int*)(s_ew + 64);              // 64

    int tid = threadIdx.x;
    int e0 = blockIdx.x * TEDGE;

    // prefetch B chunk 0 (buffer 0)
    {
        const float* src = mw3;   // chunk 0 col offset 0
        #pragma unroll
        for (int t = 0; t < 4; ++t) {
            int idx = tid + t * 512;            // 0..2047 float4s
            int k = idx >> 4, c4 = idx & 15;
            unsigned sa = (unsigned)__cvta_generic_to_shared(s_B + k * 64 + c4 * 4);
            cpa16(sa, src + k * WNUM + c4 * 4);
        }
        asm volatile("cp.async.commit_group;" ::: "memory");
    }

    // load A tile duplicated: s_hd[k][e] = (h, h)
    for (int idx = tid; idx < TEDGE * HID; idx += 512) {
        int e = idx >> 7, k = idx & 127;
        float v = (e0 + e < EE) ? g_h[(e0 + e) * HID + k] : 0.f;
        s_hd[k * HPITCH + e] = dup2(v);
    }
    // per-edge operands
    for (int i = tid; i < TEDGE * NS; i += 512) {
        int e = i >> 5, j = i & 31;
        s_xs[i] = (e0 + e < EE) ? g_xnorm[esrc[e0 + e] * DD + j] : 0.f;
    }
    for (int i = tid; i < TEDGE * 48; i += 512) {
        int e = i / 48, j = i % 48;
        s_xv[i] = (e0 + e < EE) ? g_xnorm[esrc[e0 + e] * DD + NS + j] : 0.f;
    }
    for (int i = tid; i < TEDGE; i += 512) {
        int e = e0 + i;
        if (e < EE) {
            s_sh0[i] = esh[e * 4];
            s_sh1[i * 3]     = esh[e * 4 + 1];
            s_sh1[i * 3 + 1] = esh[e * 4 + 2];
            s_sh1[i * 3 + 2] = esh[e * 4 + 3];
            s_ew[i] = g_edgew[e];
            s_dst[i] = edst[e];
        } else {
            s_sh0[i] = 0.f; s_sh1[i * 3] = 0.f; s_sh1[i * 3 + 1] = 0.f; s_sh1[i * 3 + 2] = 0.f;
            s_ew[i] = 0.f; s_dst[i] = 0;
        }
    }
    for (int i = tid; i < TEDGE * 81; i += 512) s_A[i] = 0.f;
    __syncthreads();
    for (int i = tid; i < TEDGE * NV; i += 512) {
        int e = i >> 4, iv = i & 15;
        float d = s_xv[e * 48 + iv * 3]     * s_sh1[e * 3]
                + s_xv[e * 48 + iv * 3 + 1] * s_sh1[e * 3 + 1]
                + s_xv[e * 48 + iv * 3 + 2] * s_sh1[e * 3 + 2];
        s_in2[i] = A2C * ISQ3 * d;
    }

    int tx = tid & 15;          // col group: cols 4tx..4tx+3 of chunk
    int ty = tid >> 4;          // 0..31 -> edges 2ty, 2ty+1
    const u64* ha = s_hd + ty * 2;

    for (int ch = 0; ch < 36; ++ch) {
        // prefetch next chunk into other buffer
        if (ch + 1 < 36) {
            float* dstb = s_B + ((ch + 1) & 1) * 8192;
            const float* src = mw3 + (ch + 1) * 64;
            #pragma unroll
            for (int t = 0; t < 4; ++t) {
                int idx = tid + t * 512;
                int k = idx >> 4, c4 = idx & 15;
                unsigned sa = (unsigned)__cvta_generic_to_shared(dstb + k * 64 + c4 * 4);
                cpa16(sa, src + k * WNUM + c4 * 4);
            }
        }
        asm volatile("cp.async.commit_group;" ::: "memory");
        asm volatile("cp.async.wait_group 1;" ::: "memory");
        __syncthreads();   // buf[ch&1] ready; prev contraction done (s_tp free)

        // ---- GEMM: 2 edges x 4 cols per thread, FFMA2 over packed col-pairs ----
        const float* bb = s_B + (ch & 1) * 8192 + tx * 4;
        u64 a00 = 0, a01 = 0, a10 = 0, a11 = 0;
        #pragma unroll 8
        for (int k = 0; k < HID; ++k) {
            ulonglong2 av = *(const ulonglong2*)(ha + k * HPITCH);
            ulonglong2 bv = *(const ulonglong2*)(bb + k * 64);
            ffma2(a00, av.x, bv.x); ffma2(a01, av.x, bv.y);
            ffma2(a10, av.y, bv.x); ffma2(a11, av.y, bv.y);
        }
        float4 bias = *(const float4*)(mb3 + ch * 64 + tx * 4);
        {
            float2 p0 = unpk(a00), p1 = unpk(a01);
            float4 r = make_float4(p0.x + bias.x, p0.y + bias.y, p1.x + bias.z, p1.y + bias.w);
            *(float4*)(s_tp + (ty * 2) * TPITCH + tx * 4) = r;
            float2 q0 = unpk(a10), q1 = unpk(a11);
            float4 r2 = make_float4(q0.x + bias.x, q0.y + bias.y, q1.x + bias.z, q1.y + bias.w);
            *(float4*)(s_tp + (ty * 2 + 1) * TPITCH + tx * 4) = r2;
        }
        __syncthreads();   // s_tp complete

        // ---- contraction into s_A ----
        if (ch < 16) {              // w1: col = i*32+o
            int i0 = ch * 2;
            #pragma unroll
            for (int it = 0; it < 4; ++it) {
                int item = tid + it * 512;
                int e = item >> 5, o = item & 31;
                float sc = A1C * s_sh0[e];
                s_A[e * 81 + o] += sc * (s_xs[e * 32 + i0]     * s_tp[e * TPITCH + o]
                                       + s_xs[e * 32 + i0 + 1] * s_tp[e * TPITCH + 32 + o]);
            }
        } else if (ch < 24) {       // w2
            int i0 = (ch - 16) * 2;
            #pragma unroll
            for (int it = 0; it < 4; ++it) {
                int item = tid + it * 512;
                int e = item >> 5, o = item & 31;
                s_A[e * 81 + o] += s_in2[e * 16 + i0]     * s_tp[e * TPITCH + o]
                                 + s_in2[e * 16 + i0 + 1] * s_tp[e * TPITCH + 32 + o];
            }
        } else if (ch < 32) {       // w3: col = i*16+o -> msg_v += A3*t*sh1
            int i0 = (ch - 24) * 4;
            #pragma unroll
            for (int it = 0; it < 2; ++it) {
                int item = tid + it * 512;
                int e = item >> 4, o = item & 15;
                float t = 0.f;
                #pragma unroll
                for (int j = 0; j < 4; ++j)
                    t += s_xs[e * 32 + i0 + j] * s_tp[e * TPITCH + j * 16 + o];
                t *= A3C;
                s_A[e * 81 + NS + 3 * o]     += t * s_sh1[e * 3];
                s_A[e * 81 + NS + 3 * o + 1] += t * s_sh1[e * 3 + 1];
                s_A[e * 81 + NS + 3 * o + 2] += t * s_sh1[e * 3 + 2];
            }
        } else {                    // w4
            int i0 = (ch - 32) * 4;
            #pragma unroll
            for (int it = 0; it < 2; ++it) {
                int item = tid + it * 512;
                int e = item >> 4, o = item & 15;
                float sc = A4C * s_sh0[e];
                #pragma unroll
                for (int m = 0; m < 3; ++m) {
                    float t = 0.f;
                    #pragma unroll
                    for (int j = 0; j < 4; ++j)
                        t += s_xv[e * 48 + (i0 + j) * 3 + m] * s_tp[e * TPITCH + j * 16 + o];
                    s_A[e * 81 + NS + 3 * o + m] += sc * t;
                }
            }
        }
        // no trailing sync: next iteration's first sync protects s_tp and B buffer
    }
    __syncthreads();

    // scatter
    for (int item = tid; item < TEDGE * DD; item += 512) {
        int e = item / DD, d = item % DD;
        if (e0 + e < EE) {
            float v = s_A[e * 81 + d] * s_ew[e];
            atomicAdd(&g_agg[s_dst[e] * DD + d], v);
        }
    }
}

// ---------------- kD: node epilogue ----------------
__global__ void __launch_bounds__(128) kD(const float* __restrict__ x,
                                          const float* __restrict__ Ws, const float* __restrict__ Wv,
                                          const float* __restrict__ Us, const float* __restrict__ Uv,
                                          const float* __restrict__ Ss, const float* __restrict__ Sv,
                                          const float* __restrict__ resp,
                                          float* __restrict__ out) {
    __shared__ float s_x[80], s_ag[80], s_sc[48], s_vc[48], s_sg[32], s_gt[16], s_vg[48];
    int n = blockIdx.x, tid = threadIdx.x;
    if (tid < 80) {
        s_x[tid] = g_xnorm[n * DD + tid];
        float den = fmaxf(g_den[n], 1e-8f);
        s_ag[tid] = g_agg[n * DD + tid] / den;
    }
    __syncthreads();
    if (tid < 48) {
        float a = 0.f;
        #pragma unroll
        for (int i = 0; i < 32; ++i) a += s_ag[i] * Ws[i * 48 + tid];
        s_sc[tid] = a * RS32;
    } else if (tid < 96) {
        int idx = tid - 48; int o = idx / 3, m = idx % 3;
        float a = 0.f;
        #pragma unroll
        for (int i = 0; i < 16; ++i) a += s_ag[NS + i * 3 + m] * Wv[i * 16 + o];
        s_vc[idx] = a * RS16;
    }
    __syncthreads();
    if (tid < 32) s_sg[tid] = siluf(s_sc[tid]);
    else if (tid < 48) s_gt[tid - 32] = sigmf(s_sc[tid]);
    __syncthreads();
    if (tid < 48) { int o = tid / 3; s_vg[tid] = s_vc[tid] * s_gt[o]; }
    __syncthreads();
    float res = resp[0];
    if (tid < 32) {
        float u = 0.f, sf = 0.f;
        #pragma unroll
        for (int i = 0; i < 32; ++i) {
            u  += s_sg[i] * Us[i * 32 + tid];
            sf += s_x[i]  * Ss[i * 32 + tid];
        }
        out[n * DD + tid] = x[n * DD + tid] + res * ((u + sf) * RS32);
    } else if (tid < 80) {
        int idx = tid - 32; int o = idx / 3, m = idx % 3;
        float u = 0.f, sf = 0.f;
        #pragma unroll
        for (int i = 0; i < 16; ++i) {
            u  += s_vg[i * 3 + m]     * Uv[i * 16 + o];
            sf += s_x[NS + i * 3 + m] * Sv[i * 16 + o];
        }
        out[n * DD + tid] = x[n * DD + tid] + res * ((u + sf) * RS16);
    }
}

// ---------------- launch ----------------
extern "C" void kernel_launch(void* const* d_in, const int* in_sizes, int n_in,
                              void* d_out, int out_size) {
    const float* x    = (const float*)d_in[0];
    const int*   esrc = (const int*)d_in[1];
    const int*   edst = (const int*)d_in[2];
    const float* esh  = (const float*)d_in[3];
    const float* erbf = (const float*)d_in[4];
    const float* elen = (const float*)d_in[5];
    const float* nw   = (const float*)d_in[6];
    const float* nb   = (const float*)d_in[7];
    const float* mw1  = (const float*)d_in[8];
    const float* mb1  = (const float*)d_in[9];
    const float* mw2  = (const float*)d_in[10];
    const float* mb2  = (const float*)d_in[11];
    const float* mw3  = (const float*)d_in[12];
    const float* mb3  = (const float*)d_in[13];
    const float* gw1  = (const float*)d_in[14];
    const float* gb1  = (const float*)d_in[15];
    const float* gw2  = (const float*)d_in[16];
    const float* gb2  = (const float*)d_in[17];
    const float* Ws   = (const float*)d_in[18];
    const float* Wv   = (const float*)d_in[19];
    const float* Us   = (const float*)d_in[20];
    const float* Uv   = (const float*)d_in[21];
    const float* Ss   = (const float*)d_in[22];
    const float* Sv   = (const float*)d_in[23];
    const float* resp = (const float*)d_in[24];
    float* out = (float*)d_out;

    int smemB = (16 * HID + HID * HID + 16 * HID + HID * 4 + 2 * 152) * 4;
    int smemC = 128 * HPITCH * 8
              + (2 * 128 * 64 + 64 * TPITCH + 64 * 81 + 64 * 32 + 64 * 16 + 64 * 48
                 + 64 + 64 * 3 + 64 + 64) * 4;
    cudaFuncSetAttribute(kB, cudaFuncAttributeMaxDynamicSharedMemorySize, smemB);
    cudaFuncSetAttribute(kC, cudaFuncAttributeMaxDynamicSharedMemorySize, smemC);

    kZ<<<(NN * DD + 255) / 256, 256>>>();
    kA<<<(NN * 32 + 255) / 256, 256>>>(x, nw, nb);
    kB<<<296, 256, smemB>>>(erbf, elen, edst, mw1, mb1, mw2, mb2, gw1, gb1, gw2, gb2);
    kC<<<(EE + TEDGE - 1) / TEDGE, 512, smemC>>>(esrc, edst, esh, mw3, mb3);
    kD<<<NN, 128>>>(x, Ws, Wv, Us, Uv, Ss, Sv, resp, out);
}

// round 5
// speedup vs baseline: 1.8614x; 1.8614x over previous
#include <cuda_runtime.h>
#include <math.h>

#define NN 3200
#define EE 50000
#define NS 32
#define NV 16
#define DD 80
#define HID 128
#define WNUM 2304
#define EPS 1e-8f
#define A1C 0.125f
#define A2C 0.17677669529663687f
#define A3C 0.125f
#define A4C 0.17677669529663687f
#define ISQ3 0.5773502691896258f
#define PI_F 3.14159265358979323846f
#define RS32 0.17677669529663687f
#define RS16 0.25f

typedef unsigned long long u64;

// ---------------- scratch ----------------
__device__ float g_xnorm[NN * DD];
__device__ float g_h[EE * HID];
__device__ float g_edgew[EE];
__device__ float g_agg[NN * DD];
__device__ float g_den[NN];

__device__ __forceinline__ float siluf(float x) { return x / (1.f + __expf(-x)); }
__device__ __forceinline__ float sigmf(float x) { return 1.f / (1.f + __expf(-x)); }

__device__ __forceinline__ u64 dup2(float x) {
    u64 r; asm("mov.b64 %0, {%1, %1};" : "=l"(r) : "f"(x)); return r;
}
__device__ __forceinline__ void ffma2(u64& d, u64 a, u64 b) {
    asm("fma.rn.f32x2 %0, %1, %2, %0;" : "+l"(d) : "l"(a), "l"(b));
}
__device__ __forceinline__ float2 unpk(u64 v) {
    float2 r; asm("mov.b64 {%0, %1}, %2;" : "=f"(r.x), "=f"(r.y) : "l"(v)); return r;
}
__device__ __forceinline__ void cpa16(unsigned sa, const void* g) {
    asm volatile("cp.async.cg.shared.global [%0], [%1], 16;" :: "r"(sa), "l"(g));
}

// ---------------- kZ ----------------
__global__ void kZ() {
    int i = blockIdx.x * 256 + threadIdx.x;
    if (i < NN * DD) g_agg[i] = 0.f;
    if (i < NN) g_den[i] = 0.f;
}

// ---------------- kA: irrep norm ----------------
__global__ void __launch_bounds__(256) kA(const float* __restrict__ x,
                                          const float* __restrict__ nw,
                                          const float* __restrict__ nb) {
    int warp = (blockIdx.x * blockDim.x + threadIdx.x) >> 5;
    int lane = threadIdx.x & 31;
    if (warp >= NN) return;
    const float* xr = x + warp * DD;
    float s = xr[lane];
    float m = s;
    #pragma unroll
    for (int o = 16; o; o >>= 1) m += __shfl_xor_sync(0xffffffffu, m, o);
    m *= (1.f / 32.f);
    float d = s - m;
    float v = d * d;
    #pragma unroll
    for (int o = 16; o; o >>= 1) v += __shfl_xor_sync(0xffffffffu, v, o);
    v *= (1.f / 32.f);
    float sn = d * rsqrtf(v + EPS);
    g_xnorm[warp * DD + lane] = sn * nw[lane] + nb[lane];
    if (lane < NV) {
        int b = NS + lane * 3;
        float a0 = xr[b], a1 = xr[b + 1], a2 = xr[b + 2];
        float r = rsqrtf((a0 * a0 + a1 * a1 + a2 * a2) * (1.f / 3.f) + EPS);
        int gb = warp * DD + b;
        g_xnorm[gb]     = a0 * r * nw[b]     + nb[b];
        g_xnorm[gb + 1] = a1 * r * nw[b + 1] + nb[b + 1];
        g_xnorm[gb + 2] = a2 * r * nw[b + 2] + nb[b + 2];
    }
}

// ---------------- kB: edge MLP + gate + cutoff + den (verified) ----------------
#define KB_GROUPS 592
__global__ void __launch_bounds__(256) kB(const float* __restrict__ rbf,
                                          const float* __restrict__ elen,
                                          const int* __restrict__ edst,
                                          const float* __restrict__ mw1, const float* __restrict__ mb1,
                                          const float* __restrict__ mw2, const float* __restrict__ mb2,
                                          const float* __restrict__ gw1, const float* __restrict__ gb1,
                                          const float* __restrict__ gw2, const float* __restrict__ gb2) {
    extern __shared__ float sm[];
    float* s_mw1 = sm;
    float* s_mw2 = s_mw1 + 16 * HID;
    float* s_gw1 = s_mw2 + HID * HID;
    float* s_gw2 = s_gw1 + 16 * HID;
    float* s_mb1 = s_gw2 + HID;
    float* s_mb2 = s_mb1 + HID;
    float* s_gb1 = s_mb2 + HID;
    float* s_grp = s_gb1 + HID;

    int tid = threadIdx.x;
    for (int i = tid; i < 16 * HID; i += 256) { s_mw1[i] = mw1[i]; s_gw1[i] = gw1[i]; }
    for (int i = tid; i < HID * HID; i += 256) s_mw2[i] = mw2[i];
    for (int i = tid; i < HID; i += 256) {
        s_gw2[i] = gw2[i]; s_mb1[i] = mb1[i]; s_mb2[i] = mb2[i]; s_gb1[i] = gb1[i];
    }
    int sub = tid >> 7;
    int c = tid & 127;
    float* s_rbf = s_grp + sub * 152;
    float* s_h1  = s_rbf + 16;
    float* s_red = s_h1 + 128;
    __syncthreads();

    int gid = blockIdx.x * 2 + sub;
    int iters = (EE + KB_GROUPS - 1) / KB_GROUPS;
    float gb2v = gb2[0];
    for (int it = 0; it < iters; ++it) {
        int e = it * KB_GROUPS + gid;
        bool ok = (e < EE);
        if (ok && c < 16) s_rbf[c] = rbf[e * 16 + c];
        __syncthreads();
        if (ok) {
            float a1 = s_mb1[c], ag = s_gb1[c];
            #pragma unroll
            for (int r = 0; r < 16; ++r) {
                float rv = s_rbf[r];
                a1 += rv * s_mw1[r * HID + c];
                ag += rv * s_gw1[r * HID + c];
            }
            a1 = siluf(a1);
            ag = siluf(ag);
            s_h1[c] = a1;
            float p = ag * s_gw2[c];
            #pragma unroll
            for (int o = 16; o; o >>= 1) p += __shfl_xor_sync(0xffffffffu, p, o);
            if ((c & 31) == 0) s_red[c >> 5] = p;
        }
        __syncthreads();
        if (ok) {
            float a = s_mb2[c];
            #pragma unroll 8
            for (int k = 0; k < HID; ++k) a += s_h1[k] * s_mw2[k * HID + c];
            g_h[e * HID + c] = siluf(a);
            if (c == 0) {
                float gsum = s_red[0] + s_red[1] + s_red[2] + s_red[3];
                float gate = sigmf(gsum + gb2v);
                float len = elen[e];
                float cut = (len <= 5.0f) ? 0.5f * (__cosf(PI_F * len * 0.2f) + 1.0f) : 0.0f;
                float ew = cut * gate;
                g_edgew[e] = ew;
                atomicAdd(&g_den[edst[e]], ew);
            }
        }
        __syncthreads();
    }
}

// ---------------- kC: edge-pair FFMA2 GEMM + contraction + scatter ----------------
// 256 threads, 128-edge tile, 36 chunks of 64 cols.
// A tile: u64 edge-pairs s_hp[k][64 pairs]. B chunk: raw float [128][64], single
// buffer; cp.async for chunk ch+1 issued after the post-GEMM sync (overlaps
// contraction). Per thread per k: 3 LDS.128, 4 dup movs, 16 FFMA2.
#define TEDGE 128
__global__ void __launch_bounds__(256) kC(const int* __restrict__ esrc,
                                          const int* __restrict__ edst,
                                          const float* __restrict__ esh,
                                          const float* __restrict__ mw3,
                                          const float* __restrict__ mb3) {
    extern __shared__ char smraw[];
    u64*   s_hp  = (u64*)smraw;                    // [128][64] edge-pair A   65536B
    float* s_B   = (float*)(s_hp + 128 * 64);      // [128][64] raw B chunk   32768B
    float* s_tp  = s_B + 128 * 64;                 // [128][64] tpw tile      32768B
    float* s_A   = s_tp + 128 * 64;                // [128][81] msg accum     41472B
    float* s_xs  = s_A + 128 * 81;                 // [128][32]               16384B
    float* s_in2 = s_xs + 128 * 32;                // [128][16]                8192B
    float* s_xv  = s_in2 + 128 * 16;               // [128][48]               24576B
    float* s_sh0 = s_xv + 128 * 48;                // 128
    float* s_sh1 = s_sh0 + 128;                    // [128][3]
    float* s_ew  = s_sh1 + 128 * 3;                // 128
    int*   s_dst = (int*)(s_ew + 128);             // 128

    int tid = threadIdx.x;
    int e0 = blockIdx.x * TEDGE;

    // prefetch B chunk 0
    #pragma unroll
    for (int t = 0; t < 8; ++t) {
        int idx = tid + t * 256;          // 0..2047 float4s
        int k = idx >> 4, c4 = idx & 15;
        unsigned sa = (unsigned)__cvta_generic_to_shared(s_B + k * 64 + c4 * 4);
        cpa16(sa, mw3 + k * WNUM + c4 * 4);
    }
    asm volatile("cp.async.commit_group;" ::: "memory");

    // load A tile edge-pair-packed: float view addr = k*128 + e
    {
        float* hf = (float*)s_hp;
        for (int idx = tid; idx < TEDGE * HID; idx += 256) {
            int e = idx & 127, k = idx >> 7;
            hf[k * 128 + e] = (e0 + e < EE) ? g_h[(e0 + e) * HID + k] : 0.f;
        }
    }
    // per-edge operands
    for (int i = tid; i < TEDGE * NS; i += 256) {
        int e = i >> 5, j = i & 31;
        s_xs[i] = (e0 + e < EE) ? g_xnorm[esrc[e0 + e] * DD + j] : 0.f;
    }
    for (int i = tid; i < TEDGE * 48; i += 256) {
        int e = i / 48, j = i % 48;
        s_xv[i] = (e0 + e < EE) ? g_xnorm[esrc[e0 + e] * DD + NS + j] : 0.f;
    }
    for (int i = tid; i < TEDGE; i += 256) {
        int e = e0 + i;
        if (e < EE) {
            s_sh0[i] = esh[e * 4];
            s_sh1[i * 3]     = esh[e * 4 + 1];
            s_sh1[i * 3 + 1] = esh[e * 4 + 2];
            s_sh1[i * 3 + 2] = esh[e * 4 + 3];
            s_ew[i] = g_edgew[e];
            s_dst[i] = edst[e];
        } else {
            s_sh0[i] = 0.f; s_sh1[i * 3] = 0.f; s_sh1[i * 3 + 1] = 0.f; s_sh1[i * 3 + 2] = 0.f;
            s_ew[i] = 0.f; s_dst[i] = 0;
        }
    }
    for (int i = tid; i < TEDGE * 81; i += 256) s_A[i] = 0.f;
    __syncthreads();
    for (int i = tid; i < TEDGE * NV; i += 256) {
        int e = i >> 4, iv = i & 15;
        float d = s_xv[e * 48 + iv * 3]     * s_sh1[e * 3]
                + s_xv[e * 48 + iv * 3 + 1] * s_sh1[e * 3 + 1]
                + s_xv[e * 48 + iv * 3 + 2] * s_sh1[e * 3 + 2];
        s_in2[i] = A2C * ISQ3 * d;
    }

    int tx = tid & 15;          // cols tx*4 .. tx*4+3
    int ty = tid >> 4;          // edge-pairs ty*4 .. ty*4+3 (edges 8ty..8ty+7)
    const u64* ap = s_hp + ty * 4;

    for (int ch = 0; ch < 36; ++ch) {
        asm volatile("cp.async.wait_group 0;" ::: "memory");
        __syncthreads();   // chunk ch fully in s_B; prev contraction done (s_tp free)

        // ---- GEMM: 4 edge-pairs x 4 cols per thread ----
        u64 acc[4][4];
        #pragma unroll
        for (int p = 0; p < 4; ++p)
            #pragma unroll
            for (int c = 0; c < 4; ++c) acc[p][c] = 0ULL;
        #pragma unroll 4
        for (int k = 0; k < HID; ++k) {
            ulonglong2 av0 = *(const ulonglong2*)(ap + k * 64);
            ulonglong2 av1 = *(const ulonglong2*)(ap + k * 64 + 2);
            float4 bf = *(const float4*)(s_B + k * 64 + tx * 4);
            u64 b0 = dup2(bf.x), b1 = dup2(bf.y), b2 = dup2(bf.z), b3 = dup2(bf.w);
            ffma2(acc[0][0], av0.x, b0); ffma2(acc[0][1], av0.x, b1);
            ffma2(acc[0][2], av0.x, b2); ffma2(acc[0][3], av0.x, b3);
            ffma2(acc[1][0], av0.y, b0); ffma2(acc[1][1], av0.y, b1);
            ffma2(acc[1][2], av0.y, b2); ffma2(acc[1][3], av0.y, b3);
            ffma2(acc[2][0], av1.x, b0); ffma2(acc[2][1], av1.x, b1);
            ffma2(acc[2][2], av1.x, b2); ffma2(acc[2][3], av1.x, b3);
            ffma2(acc[3][0], av1.y, b0); ffma2(acc[3][1], av1.y, b1);
            ffma2(acc[3][2], av1.y, b2); ffma2(acc[3][3], av1.y, b3);
        }
        float4 bias = *(const float4*)(mb3 + ch * 64 + tx * 4);
        #pragma unroll
        for (int p = 0; p < 4; ++p) {
            float2 u0 = unpk(acc[p][0]), u1 = unpk(acc[p][1]);
            float2 u2 = unpk(acc[p][2]), u3 = unpk(acc[p][3]);
            int r0 = 8 * ty + 2 * p;
            *(float4*)(s_tp + r0 * 64 + tx * 4) =
                make_float4(u0.x + bias.x, u1.x + bias.y, u2.x + bias.z, u3.x + bias.w);
            *(float4*)(s_tp + (r0 + 1) * 64 + tx * 4) =
                make_float4(u0.y + bias.x, u1.y + bias.y, u2.y + bias.z, u3.y + bias.w);
        }
        __syncthreads();   // s_tp complete; GEMM done reading s_B

        // prefetch next chunk (overlaps contraction)
        if (ch + 1 < 36) {
            const float* src = mw3 + (ch + 1) * 64;
            #pragma unroll
            for (int t = 0; t < 8; ++t) {
                int idx = tid + t * 256;
                int k = idx >> 4, c4 = idx & 15;
                unsigned sa = (unsigned)__cvta_generic_to_shared(s_B + k * 64 + c4 * 4);
                cpa16(sa, src + k * WNUM + c4 * 4);
            }
        }
        asm volatile("cp.async.commit_group;" ::: "memory");

        // ---- contraction into s_A ----
        if (ch < 16) {              // w1: col = i*32+o
            int i0 = ch * 2;
            #pragma unroll
            for (int it = 0; it < 16; ++it) {
                int item = tid + it * 256;
                int e = item >> 5, o = item & 31;
                float sc = A1C * s_sh0[e];
                s_A[e * 81 + o] += sc * (s_xs[e * 32 + i0]     * s_tp[e * 64 + o]
                                       + s_xs[e * 32 + i0 + 1] * s_tp[e * 64 + 32 + o]);
            }
        } else if (ch < 24) {       // w2
            int i0 = (ch - 16) * 2;
            #pragma unroll
            for (int it = 0; it < 16; ++it) {
                int item = tid + it * 256;
                int e = item >> 5, o = item & 31;
                s_A[e * 81 + o] += s_in2[e * 16 + i0]     * s_tp[e * 64 + o]
                                 + s_in2[e * 16 + i0 + 1] * s_tp[e * 64 + 32 + o];
            }
        } else if (ch < 32) {       // w3: col = i*16+o -> msg_v += A3*t*sh1
            int i0 = (ch - 24) * 4;
            #pragma unroll
            for (int it = 0; it < 8; ++it) {
                int item = tid + it * 256;
                int e = item >> 4, o = item & 15;
                float t = 0.f;
                #pragma unroll
                for (int j = 0; j < 4; ++j)
                    t += s_xs[e * 32 + i0 + j] * s_tp[e * 64 + j * 16 + o];
                t *= A3C;
                s_A[e * 81 + NS + 3 * o]     += t * s_sh1[e * 3];
                s_A[e * 81 + NS + 3 * o + 1] += t * s_sh1[e * 3 + 1];
                s_A[e * 81 + NS + 3 * o + 2] += t * s_sh1[e * 3 + 2];
            }
        } else {                    // w4
            int i0 = (ch - 32) * 4;
            #pragma unroll
            for (int it = 0; it < 8; ++it) {
                int item = tid + it * 256;
                int e = item >> 4, o = item & 15;
                float sc = A4C * s_sh0[e];
                #pragma unroll
                for (int m = 0; m < 3; ++m) {
                    float t = 0.f;
                    #pragma unroll
                    for (int j = 0; j < 4; ++j)
                        t += s_xv[e * 48 + (i0 + j) * 3 + m] * s_tp[e * 64 + j * 16 + o];
                    s_A[e * 81 + NS + 3 * o + m] += sc * t;
                }
            }
        }
        // next iteration's sync (after wait_group) protects s_tp/s_A/s_B ordering
    }
    __syncthreads();

    // scatter
    for (int item = tid; item < TEDGE * DD; item += 256) {
        int e = item / DD, d = item % DD;
        if (e0 + e < EE) {
            float v = s_A[e * 81 + d] * s_ew[e];
            atomicAdd(&g_agg[s_dst[e] * DD + d], v);
        }
    }
}

// ---------------- kD: node epilogue ----------------
__global__ void __launch_bounds__(128) kD(const float* __restrict__ x,
                                          const float* __restrict__ Ws, const float* __restrict__ Wv,
                                          const float* __restrict__ Us, const float* __restrict__ Uv,
                                          const float* __restrict__ Ss, const float* __restrict__ Sv,
                                          const float* __restrict__ resp,
                                          float* __restrict__ out) {
    __shared__ float s_x[80], s_ag[80], s_sc[48], s_vc[48], s_sg[32], s_gt[16], s_vg[48];
    int n = blockIdx.x, tid = threadIdx.x;
    if (tid < 80) {
        s_x[tid] = g_xnorm[n * DD + tid];
        float den = fmaxf(g_den[n], 1e-8f);
        s_ag[tid] = g_agg[n * DD + tid] / den;
    }
    __syncthreads();
    if (tid < 48) {
        float a = 0.f;
        #pragma unroll
        for (int i = 0; i < 32; ++i) a += s_ag[i] * Ws[i * 48 + tid];
        s_sc[tid] = a * RS32;
    } else if (tid < 96) {
        int idx = tid - 48; int o = idx / 3, m = idx % 3;
        float a = 0.f;
        #pragma unroll
        for (int i = 0; i < 16; ++i) a += s_ag[NS + i * 3 + m] * Wv[i * 16 + o];
        s_vc[idx] = a * RS16;
    }
    __syncthreads();
    if (tid < 32) s_sg[tid] = siluf(s_sc[tid]);
    else if (tid < 48) s_gt[tid - 32] = sigmf(s_sc[tid]);
    __syncthreads();
    if (tid < 48) { int o = tid / 3; s_vg[tid] = s_vc[tid] * s_gt[o]; }
    __syncthreads();
    float res = resp[0];
    if (tid < 32) {
        float u = 0.f, sf = 0.f;
        #pragma unroll
        for (int i = 0; i < 32; ++i) {
            u  += s_sg[i] * Us[i * 32 + tid];
            sf += s_x[i]  * Ss[i * 32 + tid];
        }
        out[n * DD + tid] = x[n * DD + tid] + res * ((u + sf) * RS32);
    } else if (tid < 80) {
        int idx = tid - 32; int o = idx / 3, m = idx % 3;
        float u = 0.f, sf = 0.f;
        #pragma unroll
        for (int i = 0; i < 16; ++i) {
            u  += s_vg[i * 3 + m]     * Uv[i * 16 + o];
            sf += s_x[NS + i * 3 + m] * Sv[i * 16 + o];
        }
        out[n * DD + tid] = x[n * DD + tid] + res * ((u + sf) * RS16);
    }
}

// ---------------- launch ----------------
extern "C" void kernel_launch(void* const* d_in, const int* in_sizes, int n_in,
                              void* d_out, int out_size) {
    const float* x    = (const float*)d_in[0];
    const int*   esrc = (const int*)d_in[1];
    const int*   edst = (const int*)d_in[2];
    const float* esh  = (const float*)d_in[3];
    const float* erbf = (const float*)d_in[4];
    const float* elen = (const float*)d_in[5];
    const float* nw   = (const float*)d_in[6];
    const float* nb   = (const float*)d_in[7];
    const float* mw1  = (const float*)d_in[8];
    const float* mb1  = (const float*)d_in[9];
    const float* mw2  = (const float*)d_in[10];
    const float* mb2  = (const float*)d_in[11];
    const float* mw3  = (const float*)d_in[12];
    const float* mb3  = (const float*)d_in[13];
    const float* gw1  = (const float*)d_in[14];
    const float* gb1  = (const float*)d_in[15];
    const float* gw2  = (const float*)d_in[16];
    const float* gb2  = (const float*)d_in[17];
    const float* Ws   = (const float*)d_in[18];
    const float* Wv   = (const float*)d_in[19];
    const float* Us   = (const float*)d_in[20];
    const float* Uv   = (const float*)d_in[21];
    const float* Ss   = (const float*)d_in[22];
    const float* Sv   = (const float*)d_in[23];
    const float* resp = (const float*)d_in[24];
    float* out = (float*)d_out;

    int smemB = (16 * HID + HID * HID + 16 * HID + HID * 4 + 2 * 152) * 4;
    int smemC = 128 * 64 * 8                       // A pairs
              + (128 * 64 + 128 * 64 + 128 * 81 + 128 * 32 + 128 * 16 + 128 * 48
                 + 128 + 128 * 3 + 128 + 128) * 4;
    cudaFuncSetAttribute(kB, cudaFuncAttributeMaxDynamicSharedMemorySize, smemB);
    cudaFuncSetAttribute(kC, cudaFuncAttributeMaxDynamicSharedMemorySize, smemC);

    kZ<<<(NN * DD + 255) / 256, 256>>>();
    kA<<<(NN * 32 + 255) / 256, 256>>>(x, nw, nb);
    kB<<<296, 256, smemB>>>(erbf, elen, edst, mw1, mb1, mw2, mb2, gw1, gb1, gw2, gb2);
    kC<<<(EE + TEDGE - 1) / TEDGE, 256, smemC>>>(esrc, edst, esh, mw3, mb3);
    kD<<<NN, 128>>>(x, Ws, Wv, Us, Uv, Ss, Sv, resp, out);
}